// round 1
// baseline (speedup 1.0000x reference)
#include <cuda_runtime.h>
#include <math.h>

// ---------------------------------------------------------------------------
// 4-qubit statevector gates, fully unrolled, compile-time indices only.
// Wire w maps to bit (3-w) of the amplitude index (wire 0 = MSB).
// ---------------------------------------------------------------------------

template<int M>
__device__ __forceinline__ void ry_gate(float sr[16], float si[16], float c, float s) {
#pragma unroll
    for (int i = 0; i < 16; i++) {
        if (!(i & M)) {
            const int j = i | M;
            float a0r = sr[i], a0i = si[i], a1r = sr[j], a1i = si[j];
            sr[i] = c * a0r - s * a1r;
            si[i] = c * a0i - s * a1i;
            sr[j] = s * a0r + c * a1r;
            si[j] = s * a0i + c * a1i;
        }
    }
}

template<int M>
__device__ __forceinline__ void rz_gate(float sr[16], float si[16], float c, float s) {
    // bit==0: multiply by exp(-i*th/2) = (c, -s); bit==1: (c, +s)
#pragma unroll
    for (int i = 0; i < 16; i++) {
        float sg = (i & M) ? s : -s;
        float rr = sr[i], ii = si[i];
        sr[i] = c * rr - sg * ii;
        si[i] = c * ii + sg * rr;
    }
}

template<int CM, int TM>
__device__ __forceinline__ void cx_gate(float sr[16], float si[16]) {
#pragma unroll
    for (int i = 0; i < 16; i++) {
        if ((i & CM) && !(i & TM)) {
            const int j = i | TM;
            float t;
            t = sr[i]; sr[i] = sr[j]; sr[j] = t;
            t = si[i]; si[i] = si[j]; si[j] = t;
        }
    }
}

// ---------------------------------------------------------------------------
// Fused kernel: one block per image. 196 active threads, one patch each.
// Sim -> 4 <Z_w> -> partial logits vs W -> block reduce -> log_softmax.
// ---------------------------------------------------------------------------

__global__ __launch_bounds__(224) void quanv_fused_kernel(
    const float* __restrict__ x,     // (B,1,28,28)
    const float* __restrict__ vp,    // (3,8)
    const float* __restrict__ W,     // (10,784)
    const float* __restrict__ bias,  // (10,)
    float* __restrict__ out)         // (B,10) log_softmax
{
    const int b   = blockIdx.x;
    const int tid = threadIdx.x;

    __shared__ float vc[24];
    __shared__ float vs[24];
    __shared__ float wsum[7][10];
    __shared__ float slog[10];
    __shared__ float slse;

    if (tid < 24) {
        float ss, cc;
        __sincosf(vp[tid] * 0.5f, &ss, &cc);
        vc[tid] = cc;
        vs[tid] = ss;
    }
    __syncthreads();

    float part[10];
#pragma unroll
    for (int c = 0; c < 10; c++) part[c] = 0.0f;

    if (tid < 196) {
        // ---- load 2x2 patch: [(r,c),(r,c+1),(r+1,c),(r+1,c+1)] ----
        const int r14 = tid / 14;
        const int c14 = tid % 14;
        const float* xb = x + (size_t)b * 784;
        const float2 top = *reinterpret_cast<const float2*>(xb + (2 * r14) * 28 + 2 * c14);
        const float2 bot = *reinterpret_cast<const float2*>(xb + (2 * r14 + 1) * 28 + 2 * c14);

        float c0, s0, c1, s1, c2, s2, c3, s3;
        __sincosf(top.x * 0.5f, &s0, &c0);
        __sincosf(top.y * 0.5f, &s1, &c1);
        __sincosf(bot.x * 0.5f, &s2, &c2);
        __sincosf(bot.y * 0.5f, &s3, &c3);

        // ---- encoder product state: amp(b0b1b2b3) = prod (bw ? s : c) ----
        float p01[4] = {c0 * c1, c0 * s1, s0 * c1, s0 * s1};
        float p23[4] = {c2 * c3, c2 * s3, s2 * c3, s2 * s3};
        float sr[16], si[16];
#pragma unroll
        for (int i = 0; i < 16; i++) {
            sr[i] = p01[i >> 2] * p23[i & 3];
            si[i] = 0.0f;
        }

        // ---- 3 variational layers ----
#pragma unroll
        for (int l = 0; l < 3; l++) {
            const float* lc = vc + l * 8;
            const float* ls = vs + l * 8;
            // wire i: RY(p[i]) then RZ(p[i+1])
            ry_gate<8>(sr, si, lc[0], ls[0]); rz_gate<8>(sr, si, lc[1], ls[1]);
            ry_gate<4>(sr, si, lc[1], ls[1]); rz_gate<4>(sr, si, lc[2], ls[2]);
            ry_gate<2>(sr, si, lc[2], ls[2]); rz_gate<2>(sr, si, lc[3], ls[3]);
            ry_gate<1>(sr, si, lc[3], ls[3]); rz_gate<1>(sr, si, lc[4], ls[4]);
            // CX ring: (0,1),(1,2),(2,3),(3,0)
            cx_gate<8, 4>(sr, si);
            cx_gate<4, 2>(sr, si);
            cx_gate<2, 1>(sr, si);
            cx_gate<1, 8>(sr, si);
        }

        // ---- expectations <Z_w> ----
        float pr[16];
#pragma unroll
        for (int i = 0; i < 16; i++) pr[i] = sr[i] * sr[i] + si[i] * si[i];

        float e[4];
#pragma unroll
        for (int w = 0; w < 4; w++) {
            const int m = 8 >> w;
            float acc = 0.0f;
#pragma unroll
            for (int i = 0; i < 16; i++) acc += (i & m) ? -pr[i] : pr[i];
            e[w] = acc;
        }

        // ---- partial logits: features of this patch live at cols 4*tid..4*tid+3 ----
        const int fbase = 4 * tid;
#pragma unroll
        for (int c = 0; c < 10; c++) {
            const float* wr = W + c * 784 + fbase;
            float acc;
            acc = e[0] * __ldg(wr + 0);
            acc = fmaf(e[1], __ldg(wr + 1), acc);
            acc = fmaf(e[2], __ldg(wr + 2), acc);
            acc = fmaf(e[3], __ldg(wr + 3), acc);
            part[c] = acc;
        }
    }

    // ---- block reduction: warp shuffle then cross-warp via smem ----
#pragma unroll
    for (int c = 0; c < 10; c++) {
#pragma unroll
        for (int off = 16; off > 0; off >>= 1)
            part[c] += __shfl_xor_sync(0xffffffffu, part[c], off);
    }
    const int warp = tid >> 5;
    const int lane = tid & 31;
    if (lane == 0) {
#pragma unroll
        for (int c = 0; c < 10; c++) wsum[warp][c] = part[c];
    }
    __syncthreads();

    if (tid < 10) {
        float s = bias[tid];
#pragma unroll
        for (int w = 0; w < 7; w++) s += wsum[w][tid];
        slog[tid] = s;
    }
    __syncthreads();

    if (tid == 0) {
        float mx = slog[0];
#pragma unroll
        for (int c = 1; c < 10; c++) mx = fmaxf(mx, slog[c]);
        float se = 0.0f;
#pragma unroll
        for (int c = 0; c < 10; c++) se += expf(slog[c] - mx);
        slse = mx + logf(se);
    }
    __syncthreads();

    if (tid < 10) out[(size_t)b * 10 + tid] = slog[tid] - slse;
}

extern "C" void kernel_launch(void* const* d_in, const int* in_sizes, int n_in,
                              void* d_out, int out_size) {
    const float* x    = (const float*)d_in[0];   // (B,1,28,28)
    const float* vp   = (const float*)d_in[1];   // (3,8)
    const float* W    = (const float*)d_in[2];   // (10,784)
    const float* bias = (const float*)d_in[3];   // (10,)
    float* out = (float*)d_out;

    const int B = in_sizes[0] / 784;
    quanv_fused_kernel<<<B, 224>>>(x, vp, W, bias, out);
}

// round 2
// speedup vs baseline: 1.2581x; 1.2581x over previous
#include <cuda_runtime.h>
#include <math.h>

// ---------------------------------------------------------------------------
// Gate templates (compile-time masks). Wire w <-> bit (3-w) of amp index.
// ---------------------------------------------------------------------------
template<int M>
__device__ __forceinline__ void ry_gate(float sr[16], float si[16], float c, float s) {
#pragma unroll
    for (int i = 0; i < 16; i++) {
        if (!(i & M)) {
            const int j = i | M;
            float a0r = sr[i], a0i = si[i], a1r = sr[j], a1i = si[j];
            sr[i] = c * a0r - s * a1r;
            si[i] = c * a0i - s * a1i;
            sr[j] = s * a0r + c * a1r;
            si[j] = s * a0i + c * a1i;
        }
    }
}

template<int M>
__device__ __forceinline__ void rz_gate(float sr[16], float si[16], float c, float s) {
#pragma unroll
    for (int i = 0; i < 16; i++) {
        float sg = (i & M) ? s : -s;
        float rr = sr[i], ii = si[i];
        sr[i] = c * rr - sg * ii;
        si[i] = c * ii + sg * rr;
    }
}

template<int CM, int TM>
__device__ __forceinline__ void cx_gate(float sr[16], float si[16]) {
#pragma unroll
    for (int i = 0; i < 16; i++) {
        if ((i & CM) && !(i & TM)) {
            const int j = i | TM;
            float t;
            t = sr[i]; sr[i] = sr[j]; sr[j] = t;
            t = si[i]; si[i] = si[j]; si[j] = t;
        }
    }
}

// Coefficient tensor: A[w][a12][a34], padded rows of 12 for float4 loads.
__device__ float g_A[4 * 9 * 12];

// ---------------------------------------------------------------------------
// Precompute kernel (1 block, 324 threads): build U, O_w = U^dag Z_w U,
// then multilinear coefficients A_w over the (1, cos d, sin d) basis.
// ---------------------------------------------------------------------------
__global__ void precompute_A_kernel(const float* __restrict__ vp) {
    __shared__ float vc[24], vs[24];
    __shared__ float Ur[16][16], Ui[16][16];   // [amp k][column j]
    __shared__ float ReO[4][16][16];

    const int tid = threadIdx.x;

    if (tid < 24) {
        float ss, cc;
        __sincosf(vp[tid] * 0.5f, &ss, &cc);
        vc[tid] = cc;
        vs[tid] = ss;
    }
    __syncthreads();

    // --- U columns: apply 3 variational layers to basis state |tid> ---
    if (tid < 16) {
        float sr[16], si[16];
#pragma unroll
        for (int i = 0; i < 16; i++) { sr[i] = 0.0f; si[i] = 0.0f; }
        sr[tid] = 1.0f;

#pragma unroll
        for (int l = 0; l < 3; l++) {
            const float* lc = vc + l * 8;
            const float* ls = vs + l * 8;
            ry_gate<8>(sr, si, lc[0], ls[0]); rz_gate<8>(sr, si, lc[1], ls[1]);
            ry_gate<4>(sr, si, lc[1], ls[1]); rz_gate<4>(sr, si, lc[2], ls[2]);
            ry_gate<2>(sr, si, lc[2], ls[2]); rz_gate<2>(sr, si, lc[3], ls[3]);
            ry_gate<1>(sr, si, lc[3], ls[3]); rz_gate<1>(sr, si, lc[4], ls[4]);
            cx_gate<8, 4>(sr, si);
            cx_gate<4, 2>(sr, si);
            cx_gate<2, 1>(sr, si);
            cx_gate<1, 8>(sr, si);
        }
#pragma unroll
        for (int k = 0; k < 16; k++) { Ur[k][tid] = sr[k]; Ui[k][tid] = si[k]; }
    }
    __syncthreads();

    // --- Re(O_w)[i][j] = sum_k z_w(k) (Ur[k][i]Ur[k][j] + Ui[k][i]Ui[k][j]) ---
    if (tid < 256) {
        const int i = tid >> 4;
        const int j = tid & 15;
        float acc[4] = {0.0f, 0.0f, 0.0f, 0.0f};
#pragma unroll
        for (int k = 0; k < 16; k++) {
            float t = Ur[k][i] * Ur[k][j] + Ui[k][i] * Ui[k][j];
#pragma unroll
            for (int w = 0; w < 4; w++)
                acc[w] += (k & (8 >> w)) ? -t : t;
        }
#pragma unroll
        for (int w = 0; w < 4; w++) ReO[w][i][j] = acc[w];
    }
    __syncthreads();

    // --- A_w[a] = (1/16) sum_i (-1)^{pc(i & zm)} ReO_w[i][i ^ xm] ---
    if (tid < 324) {
        const int w = tid / 81;
        const int a = tid % 81;
        const int a0 = a / 27, a1 = (a / 9) % 3, a2 = (a / 3) % 3, a3 = a % 3;
        const int zm = (a0 == 1 ? 8 : 0) | (a1 == 1 ? 4 : 0) | (a2 == 1 ? 2 : 0) | (a3 == 1 ? 1 : 0);
        const int xm = (a0 == 2 ? 8 : 0) | (a1 == 2 ? 4 : 0) | (a2 == 2 ? 2 : 0) | (a3 == 2 ? 1 : 0);
        float acc = 0.0f;
#pragma unroll
        for (int i = 0; i < 16; i++) {
            float v = ReO[w][i][i ^ xm];
            acc += (__popc(i & zm) & 1) ? -v : v;
        }
        const int a12 = a0 * 3 + a1;
        const int a34 = a2 * 3 + a3;
        g_A[(w * 9 + a12) * 12 + a34] = acc * 0.0625f;
    }
}

// ---------------------------------------------------------------------------
// Main fused kernel: one block per image, one patch per thread.
// e_w = g12^T A_w g34 with g = (1, cos d, sin d) per pixel.
// ---------------------------------------------------------------------------
__global__ __launch_bounds__(224) void quanv_fused2_kernel(
    const float* __restrict__ x,     // (B,1,28,28)
    const float* __restrict__ W,     // (10,784)
    const float* __restrict__ bias,  // (10,)
    float* __restrict__ out)         // (B,10)
{
    const int b   = blockIdx.x;
    const int tid = threadIdx.x;

    __shared__ float sA[4][9][12];
    __shared__ float wsum[7][10];
    __shared__ float slog[10];
    __shared__ float slse;

    // Stage coefficient tensor into smem (432 floats).
    for (int i = tid; i < 4 * 9 * 12; i += 224)
        ((float*)sA)[i] = g_A[i];
    __syncthreads();

    float part[10];
#pragma unroll
    for (int c = 0; c < 10; c++) part[c] = 0.0f;

    if (tid < 196) {
        const int r14 = tid / 14;
        const int c14 = tid % 14;
        const float* xb = x + (size_t)b * 784;
        const float2 top = *reinterpret_cast<const float2*>(xb + (2 * r14) * 28 + 2 * c14);
        const float2 bot = *reinterpret_cast<const float2*>(xb + (2 * r14 + 1) * 28 + 2 * c14);

        float c0, s0, c1, s1, c2, s2, c3, s3;
        __sincosf(top.x, &s0, &c0);   // full angle (double-angle identity folded into A)
        __sincosf(top.y, &s1, &c1);
        __sincosf(bot.x, &s2, &c2);
        __sincosf(bot.y, &s3, &c3);

        // g12[a0*3+a1], g34[a2*3+a3] with g = (1, cos, sin)
        float g12[9], g34[9];
        g12[0] = 1.0f; g12[1] = c1;      g12[2] = s1;
        g12[3] = c0;   g12[4] = c0 * c1; g12[5] = c0 * s1;
        g12[6] = s0;   g12[7] = s0 * c1; g12[8] = s0 * s1;
        g34[0] = 1.0f; g34[1] = c3;      g34[2] = s3;
        g34[3] = c2;   g34[4] = c2 * c3; g34[5] = c2 * s3;
        g34[6] = s2;   g34[7] = s2 * c3; g34[8] = s2 * s3;

        float e[4] = {0.0f, 0.0f, 0.0f, 0.0f};
#pragma unroll
        for (int i = 0; i < 9; i++) {
#pragma unroll
            for (int w = 0; w < 4; w++) {
                const float4 q0 = *reinterpret_cast<const float4*>(&sA[w][i][0]);
                const float4 q1 = *reinterpret_cast<const float4*>(&sA[w][i][4]);
                const float  q2 = sA[w][i][8];
                float t;
                t = q0.x * g34[0];
                t = fmaf(q0.y, g34[1], t);
                t = fmaf(q0.z, g34[2], t);
                t = fmaf(q0.w, g34[3], t);
                t = fmaf(q1.x, g34[4], t);
                t = fmaf(q1.y, g34[5], t);
                t = fmaf(q1.z, g34[6], t);
                t = fmaf(q1.w, g34[7], t);
                t = fmaf(q2,   g34[8], t);
                e[w] = fmaf(g12[i], t, e[w]);
            }
        }

        // partial logits: this patch's features at cols 4*tid..4*tid+3
        const int fbase = 4 * tid;
#pragma unroll
        for (int c = 0; c < 10; c++) {
            const float* wr = W + c * 784 + fbase;
            float acc;
            acc = e[0] * __ldg(wr + 0);
            acc = fmaf(e[1], __ldg(wr + 1), acc);
            acc = fmaf(e[2], __ldg(wr + 2), acc);
            acc = fmaf(e[3], __ldg(wr + 3), acc);
            part[c] = acc;
        }
    }

    // ---- block reduction ----
#pragma unroll
    for (int c = 0; c < 10; c++) {
#pragma unroll
        for (int off = 16; off > 0; off >>= 1)
            part[c] += __shfl_xor_sync(0xffffffffu, part[c], off);
    }
    const int warp = tid >> 5;
    const int lane = tid & 31;
    if (lane == 0) {
#pragma unroll
        for (int c = 0; c < 10; c++) wsum[warp][c] = part[c];
    }
    __syncthreads();

    if (tid < 10) {
        float s = bias[tid];
#pragma unroll
        for (int w = 0; w < 7; w++) s += wsum[w][tid];
        slog[tid] = s;
    }
    __syncthreads();

    if (tid == 0) {
        float mx = slog[0];
#pragma unroll
        for (int c = 1; c < 10; c++) mx = fmaxf(mx, slog[c]);
        float se = 0.0f;
#pragma unroll
        for (int c = 0; c < 10; c++) se += expf(slog[c] - mx);
        slse = mx + logf(se);
    }
    __syncthreads();

    if (tid < 10) out[(size_t)b * 10 + tid] = slog[tid] - slse;
}

extern "C" void kernel_launch(void* const* d_in, const int* in_sizes, int n_in,
                              void* d_out, int out_size) {
    const float* x    = (const float*)d_in[0];   // (B,1,28,28)
    const float* vp   = (const float*)d_in[1];   // (3,8)
    const float* W    = (const float*)d_in[2];   // (10,784)
    const float* bias = (const float*)d_in[3];   // (10,)
    float* out = (float*)d_out;

    const int B = in_sizes[0] / 784;
    precompute_A_kernel<<<1, 324>>>(vp);
    quanv_fused2_kernel<<<B, 224>>>(x, W, bias, out);
}

// round 3
// speedup vs baseline: 1.8371x; 1.4603x over previous
#include <cuda_runtime.h>
#include <math.h>

// ---------------------------------------------------------------------------
// Gate templates (compile-time masks). Wire w <-> bit (3-w) of amp index.
// ---------------------------------------------------------------------------
template<int M>
__device__ __forceinline__ void ry_gate(float sr[16], float si[16], float c, float s) {
#pragma unroll
    for (int i = 0; i < 16; i++) {
        if (!(i & M)) {
            const int j = i | M;
            float a0r = sr[i], a0i = si[i], a1r = sr[j], a1i = si[j];
            sr[i] = c * a0r - s * a1r;
            si[i] = c * a0i - s * a1i;
            sr[j] = s * a0r + c * a1r;
            si[j] = s * a0i + c * a1i;
        }
    }
}

template<int M>
__device__ __forceinline__ void rz_gate(float sr[16], float si[16], float c, float s) {
#pragma unroll
    for (int i = 0; i < 16; i++) {
        float sg = (i & M) ? s : -s;
        float rr = sr[i], ii = si[i];
        sr[i] = c * rr - sg * ii;
        si[i] = c * ii + sg * rr;
    }
}

template<int CM, int TM>
__device__ __forceinline__ void cx_gate(float sr[16], float si[16]) {
#pragma unroll
    for (int i = 0; i < 16; i++) {
        if ((i & CM) && !(i & TM)) {
            const int j = i | TM;
            float t;
            t = sr[i]; sr[i] = sr[j]; sr[j] = t;
            t = si[i]; si[i] = si[j]; si[j] = t;
        }
    }
}

// Coefficient tensor, layout [i(a12)][w*9 + j(a34)]: 9 rows x 36 floats.
__device__ float g_A[9 * 36];

// ---------------------------------------------------------------------------
// Precompute kernel (1 block): U, O_w = U^dag Z_w U, multilinear coeffs.
// ---------------------------------------------------------------------------
__global__ void precompute_A_kernel(const float* __restrict__ vp) {
    __shared__ float vc[24], vs[24];
    __shared__ float Ur[16][16], Ui[16][16];
    __shared__ float ReO[4][16][16];

    const int tid = threadIdx.x;

    if (tid < 24) {
        float ss, cc;
        __sincosf(vp[tid] * 0.5f, &ss, &cc);
        vc[tid] = cc;
        vs[tid] = ss;
    }
    __syncthreads();

    if (tid < 16) {
        float sr[16], si[16];
#pragma unroll
        for (int i = 0; i < 16; i++) { sr[i] = 0.0f; si[i] = 0.0f; }
        sr[tid] = 1.0f;

#pragma unroll
        for (int l = 0; l < 3; l++) {
            const float* lc = vc + l * 8;
            const float* ls = vs + l * 8;
            ry_gate<8>(sr, si, lc[0], ls[0]); rz_gate<8>(sr, si, lc[1], ls[1]);
            ry_gate<4>(sr, si, lc[1], ls[1]); rz_gate<4>(sr, si, lc[2], ls[2]);
            ry_gate<2>(sr, si, lc[2], ls[2]); rz_gate<2>(sr, si, lc[3], ls[3]);
            ry_gate<1>(sr, si, lc[3], ls[3]); rz_gate<1>(sr, si, lc[4], ls[4]);
            cx_gate<8, 4>(sr, si);
            cx_gate<4, 2>(sr, si);
            cx_gate<2, 1>(sr, si);
            cx_gate<1, 8>(sr, si);
        }
#pragma unroll
        for (int k = 0; k < 16; k++) { Ur[k][tid] = sr[k]; Ui[k][tid] = si[k]; }
    }
    __syncthreads();

    if (tid < 256) {
        const int i = tid >> 4;
        const int j = tid & 15;
        float acc[4] = {0.0f, 0.0f, 0.0f, 0.0f};
#pragma unroll
        for (int k = 0; k < 16; k++) {
            float t = Ur[k][i] * Ur[k][j] + Ui[k][i] * Ui[k][j];
#pragma unroll
            for (int w = 0; w < 4; w++)
                acc[w] += (k & (8 >> w)) ? -t : t;
        }
#pragma unroll
        for (int w = 0; w < 4; w++) ReO[w][i][j] = acc[w];
    }
    __syncthreads();

    if (tid < 324) {
        const int w = tid / 81;
        const int a = tid % 81;
        const int a0 = a / 27, a1 = (a / 9) % 3, a2 = (a / 3) % 3, a3 = a % 3;
        const int zm = (a0 == 1 ? 8 : 0) | (a1 == 1 ? 4 : 0) | (a2 == 1 ? 2 : 0) | (a3 == 1 ? 1 : 0);
        const int xm = (a0 == 2 ? 8 : 0) | (a1 == 2 ? 4 : 0) | (a2 == 2 ? 2 : 0) | (a3 == 2 ? 1 : 0);
        float acc = 0.0f;
#pragma unroll
        for (int i = 0; i < 16; i++) {
            float v = ReO[w][i][i ^ xm];
            acc += (__popc(i & zm) & 1) ? -v : v;
        }
        const int a12 = a0 * 3 + a1;
        const int a34 = a2 * 3 + a3;
        g_A[a12 * 36 + w * 9 + a34] = acc * 0.0625f;
    }
}

// ---------------------------------------------------------------------------
// Main fused kernel: one block per IMAGE PAIR. Thread t < 196 computes patch t
// of both images; A rows and W rows are loaded once and used twice.
// ---------------------------------------------------------------------------
__global__ __launch_bounds__(224) void quanv_fused3_kernel(
    const float* __restrict__ x,     // (B,1,28,28)
    const float* __restrict__ W,     // (10,784)
    const float* __restrict__ bias,  // (10,)
    float* __restrict__ out,         // (B,10)
    int B)
{
    const int b0  = 2 * blockIdx.x;
    const int b1  = b0 + 1;
    const bool has1 = (b1 < B);
    const int tid = threadIdx.x;

    __shared__ float sA[9 * 36];
    __shared__ float wsum[7][20];
    __shared__ float slog[20];
    __shared__ float slse[2];

    for (int i = tid; i < 9 * 36; i += 224)
        sA[i] = g_A[i];
    __syncthreads();

    float part0[10], part1[10];
#pragma unroll
    for (int c = 0; c < 10; c++) { part0[c] = 0.0f; part1[c] = 0.0f; }

    if (tid < 196) {
        const int r14 = tid / 14;
        const int c14 = tid % 14;
        const int off = (2 * r14) * 28 + 2 * c14;

        // ---- image 0 angles ----
        const float* xa = x + (size_t)b0 * 784;
        const float2 ta = *reinterpret_cast<const float2*>(xa + off);
        const float2 ba = *reinterpret_cast<const float2*>(xa + off + 28);

        float g12a[9], g34a[9];
        {
            float c0, s0, c1, s1, c2, s2, c3, s3;
            __sincosf(ta.x, &s0, &c0);
            __sincosf(ta.y, &s1, &c1);
            __sincosf(ba.x, &s2, &c2);
            __sincosf(ba.y, &s3, &c3);
            g12a[0] = 1.0f; g12a[1] = c1;      g12a[2] = s1;
            g12a[3] = c0;   g12a[4] = c0 * c1; g12a[5] = c0 * s1;
            g12a[6] = s0;   g12a[7] = s0 * c1; g12a[8] = s0 * s1;
            g34a[0] = 1.0f; g34a[1] = c3;      g34a[2] = s3;
            g34a[3] = c2;   g34a[4] = c2 * c3; g34a[5] = c2 * s3;
            g34a[6] = s2;   g34a[7] = s2 * c3; g34a[8] = s2 * s3;
        }

        // ---- image 1 angles ----
        float g12b[9], g34b[9];
        if (has1) {
            const float* xb = x + (size_t)b1 * 784;
            const float2 tb = *reinterpret_cast<const float2*>(xb + off);
            const float2 bb = *reinterpret_cast<const float2*>(xb + off + 28);
            float c0, s0, c1, s1, c2, s2, c3, s3;
            __sincosf(tb.x, &s0, &c0);
            __sincosf(tb.y, &s1, &c1);
            __sincosf(bb.x, &s2, &c2);
            __sincosf(bb.y, &s3, &c3);
            g12b[0] = 1.0f; g12b[1] = c1;      g12b[2] = s1;
            g12b[3] = c0;   g12b[4] = c0 * c1; g12b[5] = c0 * s1;
            g12b[6] = s0;   g12b[7] = s0 * c1; g12b[8] = s0 * s1;
            g34b[0] = 1.0f; g34b[1] = c3;      g34b[2] = s3;
            g34b[3] = c2;   g34b[4] = c2 * c3; g34b[5] = c2 * s3;
            g34b[6] = s2;   g34b[7] = s2 * c3; g34b[8] = s2 * s3;
        } else {
#pragma unroll
            for (int i = 0; i < 9; i++) { g12b[i] = 0.0f; g34b[i] = 0.0f; }
        }

        // ---- contraction: e_w = g12^T A_w g34, A row shared by both images ----
        float e0[4] = {0.f, 0.f, 0.f, 0.f};
        float e1[4] = {0.f, 0.f, 0.f, 0.f};
#pragma unroll
        for (int i = 0; i < 9; i++) {
            float av[36];
#pragma unroll
            for (int q = 0; q < 9; q++)
                *reinterpret_cast<float4*>(av + 4 * q) =
                    *reinterpret_cast<const float4*>(&sA[i * 36 + 4 * q]);
#pragma unroll
            for (int w = 0; w < 4; w++) {
                const float* aw = av + w * 9;
                float t0 = aw[0] * g34a[0];
                float t1 = aw[0] * g34b[0];
#pragma unroll
                for (int j = 1; j < 9; j++) {
                    t0 = fmaf(aw[j], g34a[j], t0);
                    t1 = fmaf(aw[j], g34b[j], t1);
                }
                e0[w] = fmaf(g12a[i], t0, e0[w]);
                e1[w] = fmaf(g12b[i], t1, e1[w]);
            }
        }

        // ---- partial logits: W float4 shared by both images ----
#pragma unroll
        for (int c = 0; c < 10; c++) {
            const float4 wv = *reinterpret_cast<const float4*>(W + c * 784 + 4 * tid);
            float a0 = e0[0] * wv.x;
            a0 = fmaf(e0[1], wv.y, a0);
            a0 = fmaf(e0[2], wv.z, a0);
            a0 = fmaf(e0[3], wv.w, a0);
            part0[c] = a0;
            float a1 = e1[0] * wv.x;
            a1 = fmaf(e1[1], wv.y, a1);
            a1 = fmaf(e1[2], wv.z, a1);
            a1 = fmaf(e1[3], wv.w, a1);
            part1[c] = a1;
        }
    }

    // ---- block reduction of 20 partials ----
#pragma unroll
    for (int c = 0; c < 10; c++) {
#pragma unroll
        for (int off = 16; off > 0; off >>= 1) {
            part0[c] += __shfl_xor_sync(0xffffffffu, part0[c], off);
            part1[c] += __shfl_xor_sync(0xffffffffu, part1[c], off);
        }
    }
    const int warp = tid >> 5;
    const int lane = tid & 31;
    if (lane == 0) {
#pragma unroll
        for (int c = 0; c < 10; c++) {
            wsum[warp][c]      = part0[c];
            wsum[warp][10 + c] = part1[c];
        }
    }
    __syncthreads();

    if (tid < 20) {
        float s = bias[tid % 10];
#pragma unroll
        for (int w = 0; w < 7; w++) s += wsum[w][tid];
        slog[tid] = s;
    }
    __syncthreads();

    if (tid < 2) {
        const float* l = slog + 10 * tid;
        float mx = l[0];
#pragma unroll
        for (int c = 1; c < 10; c++) mx = fmaxf(mx, l[c]);
        float se = 0.0f;
#pragma unroll
        for (int c = 0; c < 10; c++) se += expf(l[c] - mx);
        slse[tid] = mx + logf(se);
    }
    __syncthreads();

    if (tid < 20) {
        const int img = tid / 10;
        if (img == 0 || has1)
            out[(size_t)(b0 + img) * 10 + (tid % 10)] = slog[tid] - slse[img];
    }
}

extern "C" void kernel_launch(void* const* d_in, const int* in_sizes, int n_in,
                              void* d_out, int out_size) {
    const float* x    = (const float*)d_in[0];   // (B,1,28,28)
    const float* vp   = (const float*)d_in[1];   // (3,8)
    const float* W    = (const float*)d_in[2];   // (10,784)
    const float* bias = (const float*)d_in[3];   // (10,)
    float* out = (float*)d_out;

    const int B = in_sizes[0] / 784;
    precompute_A_kernel<<<1, 324>>>(vp);
    quanv_fused3_kernel<<<(B + 1) / 2, 224>>>(x, W, bias, out, B);
}